// round 3
// baseline (speedup 1.0000x reference)
#include <cuda_runtime.h>
#include <cuda_bf16.h>
#include <cstdint>

// Problem: B=8, S=2048, N=4, D=1024
//   mixed[b,s,i,d] = sum_j h_res[b,s,i,j] * x[b,s,j,d]
//   out = mixed * h_out[b,s,d] + h_post[b,s,i] * x[b,s,i,d]
//
// Persistent grid-stride over tokens: grid = 148 SMs * 8 CTAs = 1184 CTAs,
// 256 threads each; thread t owns float4 chunk t of D across all 4 streams.
// No shared memory, no barriers: per-token scalars (h_res 4x4, h_post 4) are
// loaded warp-uniformly (single sector, L1 broadcast).

#define TOKENS (8 * 2048)
#define D_DIM 1024
#define D4 (D_DIM / 4)   // 256
#define GRID_CTAS (148 * 8)

__global__ __launch_bounds__(256, 8)
void stream_mix_kernel(const float* __restrict__ x,
                       const float* __restrict__ h_res,
                       const float* __restrict__ h_out,
                       const float* __restrict__ h_post,
                       float* __restrict__ out) {
    const int d4 = threadIdx.x;          // 0 .. 255

    for (int tok = blockIdx.x; tok < TOKENS; tok += GRID_CTAS) {
        const float4* xb =
            reinterpret_cast<const float4*>(x + (size_t)tok * 4 * D_DIM);
        const float4* hrb =
            reinterpret_cast<const float4*>(h_res + (size_t)tok * 16);

        // Front-batch all loads (maximize MLP). Big streams use .cs
        // (evict-first streaming) — single-touch data.
        const float4 x0 = __ldcs(&xb[0 * D4 + d4]);
        const float4 x1 = __ldcs(&xb[1 * D4 + d4]);
        const float4 x2 = __ldcs(&xb[2 * D4 + d4]);
        const float4 x3 = __ldcs(&xb[3 * D4 + d4]);
        const float4 ho = __ldcs(
            &reinterpret_cast<const float4*>(h_out + (size_t)tok * D_DIM)[d4]);

        // Warp-uniform scalars (broadcast within warp; L1-cached across warps).
        const float4 hr0 = __ldg(&hrb[0]);
        const float4 hr1 = __ldg(&hrb[1]);
        const float4 hr2 = __ldg(&hrb[2]);
        const float4 hr3 = __ldg(&hrb[3]);
        const float4 hp  = __ldg(
            &reinterpret_cast<const float4*>(h_post + (size_t)tok * 4)[0]);

        float4* ob = reinterpret_cast<float4*>(out + (size_t)tok * 4 * D_DIM);

        // Stream 0
        {
            float4 o;
            o.x = (hr0.x * x0.x + hr0.y * x1.x + hr0.z * x2.x + hr0.w * x3.x) * ho.x + hp.x * x0.x;
            o.y = (hr0.x * x0.y + hr0.y * x1.y + hr0.z * x2.y + hr0.w * x3.y) * ho.y + hp.x * x0.y;
            o.z = (hr0.x * x0.z + hr0.y * x1.z + hr0.z * x2.z + hr0.w * x3.z) * ho.z + hp.x * x0.z;
            o.w = (hr0.x * x0.w + hr0.y * x1.w + hr0.z * x2.w + hr0.w * x3.w) * ho.w + hp.x * x0.w;
            __stcs(&ob[0 * D4 + d4], o);
        }
        // Stream 1
        {
            float4 o;
            o.x = (hr1.x * x0.x + hr1.y * x1.x + hr1.z * x2.x + hr1.w * x3.x) * ho.x + hp.y * x1.x;
            o.y = (hr1.x * x0.y + hr1.y * x1.y + hr1.z * x2.y + hr1.w * x3.y) * ho.y + hp.y * x1.y;
            o.z = (hr1.x * x0.z + hr1.y * x1.z + hr1.z * x2.z + hr1.w * x3.z) * ho.z + hp.y * x1.z;
            o.w = (hr1.x * x0.w + hr1.y * x1.w + hr1.z * x2.w + hr1.w * x3.w) * ho.w + hp.y * x1.w;
            __stcs(&ob[1 * D4 + d4], o);
        }
        // Stream 2
        {
            float4 o;
            o.x = (hr2.x * x0.x + hr2.y * x1.x + hr2.z * x2.x + hr2.w * x3.x) * ho.x + hp.z * x2.x;
            o.y = (hr2.x * x0.y + hr2.y * x1.y + hr2.z * x2.y + hr2.w * x3.y) * ho.y + hp.z * x2.y;
            o.z = (hr2.x * x0.z + hr2.y * x1.z + hr2.z * x2.z + hr2.w * x3.z) * ho.z + hp.z * x2.z;
            o.w = (hr2.x * x0.w + hr2.y * x1.w + hr2.z * x2.w + hr2.w * x3.w) * ho.w + hp.z * x2.w;
            __stcs(&ob[2 * D4 + d4], o);
        }
        // Stream 3
        {
            float4 o;
            o.x = (hr3.x * x0.x + hr3.y * x1.x + hr3.z * x2.x + hr3.w * x3.x) * ho.x + hp.w * x3.x;
            o.y = (hr3.x * x0.y + hr3.y * x1.y + hr3.z * x2.y + hr3.w * x3.y) * ho.y + hp.w * x3.y;
            o.z = (hr3.x * x0.z + hr3.y * x1.z + hr3.z * x2.z + hr3.w * x3.z) * ho.z + hp.w * x3.z;
            o.w = (hr3.x * x0.w + hr3.y * x1.w + hr3.z * x2.w + hr3.w * x3.w) * ho.w + hp.w * x3.w;
            __stcs(&ob[3 * D4 + d4], o);
        }
    }
}

extern "C" void kernel_launch(void* const* d_in, const int* in_sizes, int n_in,
                              void* d_out, int out_size) {
    const float* x      = (const float*)d_in[0];  // [8,2048,4,1024]
    const float* h_res  = (const float*)d_in[1];  // [8,2048,4,4]
    const float* h_out  = (const float*)d_in[2];  // [8,2048,1024]
    const float* h_post = (const float*)d_in[3];  // [8,2048,4]
    float* out = (float*)d_out;                   // [8,2048,4,1024]

    stream_mix_kernel<<<GRID_CTAS, 256>>>(x, h_res, h_out, h_post, out);
}

// round 7
// speedup vs baseline: 1.6933x; 1.6933x over previous
#include <cuda_runtime.h>
#include <cuda_bf16.h>
#include <cstdint>

// Problem: B=8, S=2048, N=4, D=1024
//   mixed[b,s,i,d] = sum_j h_res[b,s,i,j] * x[b,s,j,d]
//   out = mixed * h_out[b,s,d] + h_post[b,s,i] * x[b,s,i,d]
//
// One CTA per token (b*s). 256 threads; thread t owns float4 chunk t of D
// (D/4 = 256 chunks) across all 4 streams. CTA churn provides the MLP:
// each new CTA front-batches 5 independent 128-bit loads.
// Single-touch streams use .cs (evict-first) load/store policy.

#define TOKENS (8 * 2048)
#define D_DIM 1024
#define D4 (D_DIM / 4)   // 256

__global__ __launch_bounds__(256, 8)
void stream_mix_kernel(const float* __restrict__ x,
                       const float* __restrict__ h_res,
                       const float* __restrict__ h_out,
                       const float* __restrict__ h_post,
                       float* __restrict__ out) {
    const int tok = blockIdx.x;          // 0 .. TOKENS-1
    const int d4  = threadIdx.x;         // 0 .. 255

    __shared__ float4 s_hr[4];           // h_res rows (4x4)
    __shared__ float4 s_hp;              // h_post (4)

    if (threadIdx.x < 4) {
        s_hr[threadIdx.x] =
            reinterpret_cast<const float4*>(h_res + (size_t)tok * 16)[threadIdx.x];
    } else if (threadIdx.x == 4) {
        s_hp = reinterpret_cast<const float4*>(h_post + (size_t)tok * 4)[0];
    }

    // Big global loads issued before the barrier so they overlap the sync.
    const float4* xb =
        reinterpret_cast<const float4*>(x + (size_t)tok * 4 * D_DIM);
    const float4 x0 = __ldcs(&xb[0 * D4 + d4]);
    const float4 x1 = __ldcs(&xb[1 * D4 + d4]);
    const float4 x2 = __ldcs(&xb[2 * D4 + d4]);
    const float4 x3 = __ldcs(&xb[3 * D4 + d4]);
    const float4 ho = __ldcs(
        &reinterpret_cast<const float4*>(h_out + (size_t)tok * D_DIM)[d4]);

    __syncthreads();

    const float4 hp = s_hp;
    float4* ob = reinterpret_cast<float4*>(out + (size_t)tok * 4 * D_DIM);

    // Stream 0
    {
        const float4 hr = s_hr[0];
        float4 o;
        o.x = (hr.x * x0.x + hr.y * x1.x + hr.z * x2.x + hr.w * x3.x) * ho.x + hp.x * x0.x;
        o.y = (hr.x * x0.y + hr.y * x1.y + hr.z * x2.y + hr.w * x3.y) * ho.y + hp.x * x0.y;
        o.z = (hr.x * x0.z + hr.y * x1.z + hr.z * x2.z + hr.w * x3.z) * ho.z + hp.x * x0.z;
        o.w = (hr.x * x0.w + hr.y * x1.w + hr.z * x2.w + hr.w * x3.w) * ho.w + hp.x * x0.w;
        __stcs(&ob[0 * D4 + d4], o);
    }
    // Stream 1
    {
        const float4 hr = s_hr[1];
        float4 o;
        o.x = (hr.x * x0.x + hr.y * x1.x + hr.z * x2.x + hr.w * x3.x) * ho.x + hp.y * x1.x;
        o.y = (hr.x * x0.y + hr.y * x1.y + hr.z * x2.y + hr.w * x3.y) * ho.y + hp.y * x1.y;
        o.z = (hr.x * x0.z + hr.y * x1.z + hr.z * x2.z + hr.w * x3.z) * ho.z + hp.y * x1.z;
        o.w = (hr.x * x0.w + hr.y * x1.w + hr.z * x2.w + hr.w * x3.w) * ho.w + hp.y * x1.w;
        __stcs(&ob[1 * D4 + d4], o);
    }
    // Stream 2
    {
        const float4 hr = s_hr[2];
        float4 o;
        o.x = (hr.x * x0.x + hr.y * x1.x + hr.z * x2.x + hr.w * x3.x) * ho.x + hp.z * x2.x;
        o.y = (hr.x * x0.y + hr.y * x1.y + hr.z * x2.y + hr.w * x3.y) * ho.y + hp.z * x2.y;
        o.z = (hr.x * x0.z + hr.y * x1.z + hr.z * x2.z + hr.w * x3.z) * ho.z + hp.z * x2.z;
        o.w = (hr.x * x0.w + hr.y * x1.w + hr.z * x2.w + hr.w * x3.w) * ho.w + hp.z * x2.w;
        __stcs(&ob[2 * D4 + d4], o);
    }
    // Stream 3
    {
        const float4 hr = s_hr[3];
        float4 o;
        o.x = (hr.x * x0.x + hr.y * x1.x + hr.z * x2.x + hr.w * x3.x) * ho.x + hp.w * x3.x;
        o.y = (hr.x * x0.y + hr.y * x1.y + hr.z * x2.y + hr.w * x3.y) * ho.y + hp.w * x3.y;
        o.z = (hr.x * x0.z + hr.y * x1.z + hr.z * x2.z + hr.w * x3.z) * ho.z + hp.w * x3.z;
        o.w = (hr.x * x0.w + hr.y * x1.w + hr.z * x2.w + hr.w * x3.w) * ho.w + hp.w * x3.w;
        __stcs(&ob[3 * D4 + d4], o);
    }
}

extern "C" void kernel_launch(void* const* d_in, const int* in_sizes, int n_in,
                              void* d_out, int out_size) {
    const float* x      = (const float*)d_in[0];  // [8,2048,4,1024]
    const float* h_res  = (const float*)d_in[1];  // [8,2048,4,4]
    const float* h_out  = (const float*)d_in[2];  // [8,2048,1024]
    const float* h_post = (const float*)d_in[3];  // [8,2048,4]
    float* out = (float*)d_out;                   // [8,2048,4,1024]

    stream_mix_kernel<<<TOKENS, 256>>>(x, h_res, h_out, h_post, out);
}

// round 8
// speedup vs baseline: 1.7263x; 1.0195x over previous
#include <cuda_runtime.h>
#include <cuda_bf16.h>
#include <cstdint>

// Problem: B=8, S=2048, N=4, D=1024
//   mixed[b,s,i,d] = sum_j h_res[b,s,i,j] * x[b,s,j,d]
//   out = mixed * h_out[b,s,d] + h_post[b,s,i] * x[b,s,i,d]
//
// TWO tokens per CTA. 256 threads; thread t owns float4 chunk t of D for
// both tokens. All 10 big 128-bit loads are front-batched (MLP_p1 = 10)
// before the barrier/compute, doubling per-warp memory parallelism vs the
// one-token version while keeping the same per-SM outstanding-load count.

#define TOKENS (8 * 2048)
#define D_DIM 1024
#define D4 (D_DIM / 4)   // 256

__global__ __launch_bounds__(256)
void stream_mix_kernel2(const float* __restrict__ x,
                        const float* __restrict__ h_res,
                        const float* __restrict__ h_out,
                        const float* __restrict__ h_post,
                        float* __restrict__ out) {
    const int tok0 = blockIdx.x * 2;     // even token
    const int d4   = threadIdx.x;        // 0 .. 255

    __shared__ float4 s_hr[2][4];        // h_res rows for both tokens
    __shared__ float4 s_hp[2];           // h_post for both tokens

    const int tid = threadIdx.x;
    if (tid < 8) {
        const int t = tid >> 2;          // which token
        const int r = tid & 3;           // which row
        s_hr[t][r] = reinterpret_cast<const float4*>(
            h_res + (size_t)(tok0 + t) * 16)[r];
    } else if (tid < 10) {
        const int t = tid - 8;
        s_hp[t] = reinterpret_cast<const float4*>(
            h_post + (size_t)(tok0 + t) * 4)[0];
    }

    // Front-batch ALL big loads for both tokens (10 independent LDG.128).
    const float4* xa =
        reinterpret_cast<const float4*>(x + (size_t)tok0 * 4 * D_DIM);
    const float4* xb = xa + 4 * D4;      // next token's x block

    const float4 a0 = __ldcs(&xa[0 * D4 + d4]);
    const float4 a1 = __ldcs(&xa[1 * D4 + d4]);
    const float4 a2 = __ldcs(&xa[2 * D4 + d4]);
    const float4 a3 = __ldcs(&xa[3 * D4 + d4]);
    const float4 b0 = __ldcs(&xb[0 * D4 + d4]);
    const float4 b1 = __ldcs(&xb[1 * D4 + d4]);
    const float4 b2 = __ldcs(&xb[2 * D4 + d4]);
    const float4 b3 = __ldcs(&xb[3 * D4 + d4]);
    const float4 hoa = __ldcs(
        &reinterpret_cast<const float4*>(h_out + (size_t)tok0 * D_DIM)[d4]);
    const float4 hob = __ldcs(
        &reinterpret_cast<const float4*>(h_out + (size_t)(tok0 + 1) * D_DIM)[d4]);

    __syncthreads();

    float4* oa = reinterpret_cast<float4*>(out + (size_t)tok0 * 4 * D_DIM);
    float4* ob = oa + 4 * D4;

    // ---- Token A ----
    {
        const float4 hp = s_hp[0];
        {
            const float4 hr = s_hr[0][0];
            float4 o;
            o.x = (hr.x*a0.x + hr.y*a1.x + hr.z*a2.x + hr.w*a3.x) * hoa.x + hp.x*a0.x;
            o.y = (hr.x*a0.y + hr.y*a1.y + hr.z*a2.y + hr.w*a3.y) * hoa.y + hp.x*a0.y;
            o.z = (hr.x*a0.z + hr.y*a1.z + hr.z*a2.z + hr.w*a3.z) * hoa.z + hp.x*a0.z;
            o.w = (hr.x*a0.w + hr.y*a1.w + hr.z*a2.w + hr.w*a3.w) * hoa.w + hp.x*a0.w;
            __stcs(&oa[0 * D4 + d4], o);
        }
        {
            const float4 hr = s_hr[0][1];
            float4 o;
            o.x = (hr.x*a0.x + hr.y*a1.x + hr.z*a2.x + hr.w*a3.x) * hoa.x + hp.y*a1.x;
            o.y = (hr.x*a0.y + hr.y*a1.y + hr.z*a2.y + hr.w*a3.y) * hoa.y + hp.y*a1.y;
            o.z = (hr.x*a0.z + hr.y*a1.z + hr.z*a2.z + hr.w*a3.z) * hoa.z + hp.y*a1.z;
            o.w = (hr.x*a0.w + hr.y*a1.w + hr.z*a2.w + hr.w*a3.w) * hoa.w + hp.y*a1.w;
            __stcs(&oa[1 * D4 + d4], o);
        }
        {
            const float4 hr = s_hr[0][2];
            float4 o;
            o.x = (hr.x*a0.x + hr.y*a1.x + hr.z*a2.x + hr.w*a3.x) * hoa.x + hp.z*a2.x;
            o.y = (hr.x*a0.y + hr.y*a1.y + hr.z*a2.y + hr.w*a3.y) * hoa.y + hp.z*a2.y;
            o.z = (hr.x*a0.z + hr.y*a1.z + hr.z*a2.z + hr.w*a3.z) * hoa.z + hp.z*a2.z;
            o.w = (hr.x*a0.w + hr.y*a1.w + hr.z*a2.w + hr.w*a3.w) * hoa.w + hp.z*a2.w;
            __stcs(&oa[2 * D4 + d4], o);
        }
        {
            const float4 hr = s_hr[0][3];
            float4 o;
            o.x = (hr.x*a0.x + hr.y*a1.x + hr.z*a2.x + hr.w*a3.x) * hoa.x + hp.w*a3.x;
            o.y = (hr.x*a0.y + hr.y*a1.y + hr.z*a2.y + hr.w*a3.y) * hoa.y + hp.w*a3.y;
            o.z = (hr.x*a0.z + hr.y*a1.z + hr.z*a2.z + hr.w*a3.z) * hoa.z + hp.w*a3.z;
            o.w = (hr.x*a0.w + hr.y*a1.w + hr.z*a2.w + hr.w*a3.w) * hoa.w + hp.w*a3.w;
            __stcs(&oa[3 * D4 + d4], o);
        }
    }

    // ---- Token B ----
    {
        const float4 hp = s_hp[1];
        {
            const float4 hr = s_hr[1][0];
            float4 o;
            o.x = (hr.x*b0.x + hr.y*b1.x + hr.z*b2.x + hr.w*b3.x) * hob.x + hp.x*b0.x;
            o.y = (hr.x*b0.y + hr.y*b1.y + hr.z*b2.y + hr.w*b3.y) * hob.y + hp.x*b0.y;
            o.z = (hr.x*b0.z + hr.y*b1.z + hr.z*b2.z + hr.w*b3.z) * hob.z + hp.x*b0.z;
            o.w = (hr.x*b0.w + hr.y*b1.w + hr.z*b2.w + hr.w*b3.w) * hob.w + hp.x*b0.w;
            __stcs(&ob[0 * D4 + d4], o);
        }
        {
            const float4 hr = s_hr[1][1];
            float4 o;
            o.x = (hr.x*b0.x + hr.y*b1.x + hr.z*b2.x + hr.w*b3.x) * hob.x + hp.y*b1.x;
            o.y = (hr.x*b0.y + hr.y*b1.y + hr.z*b2.y + hr.w*b3.y) * hob.y + hp.y*b1.y;
            o.z = (hr.x*b0.z + hr.y*b1.z + hr.z*b2.z + hr.w*b3.z) * hob.z + hp.y*b1.z;
            o.w = (hr.x*b0.w + hr.y*b1.w + hr.z*b2.w + hr.w*b3.w) * hob.w + hp.y*b1.w;
            __stcs(&ob[1 * D4 + d4], o);
        }
        {
            const float4 hr = s_hr[1][2];
            float4 o;
            o.x = (hr.x*b0.x + hr.y*b1.x + hr.z*b2.x + hr.w*b3.x) * hob.x + hp.z*b2.x;
            o.y = (hr.x*b0.y + hr.y*b1.y + hr.z*b2.y + hr.w*b3.y) * hob.y + hp.z*b2.y;
            o.z = (hr.x*b0.z + hr.y*b1.z + hr.z*b2.z + hr.w*b3.z) * hob.z + hp.z*b2.z;
            o.w = (hr.x*b0.w + hr.y*b1.w + hr.z*b2.w + hr.w*b3.w) * hob.w + hp.z*b2.w;
            __stcs(&ob[2 * D4 + d4], o);
        }
        {
            const float4 hr = s_hr[1][3];
            float4 o;
            o.x = (hr.x*b0.x + hr.y*b1.x + hr.z*b2.x + hr.w*b3.x) * hob.x + hp.w*b3.x;
            o.y = (hr.x*b0.y + hr.y*b1.y + hr.z*b2.y + hr.w*b3.y) * hob.y + hp.w*b3.y;
            o.z = (hr.x*b0.z + hr.y*b1.z + hr.z*b2.z + hr.w*b3.z) * hob.z + hp.w*b3.z;
            o.w = (hr.x*b0.w + hr.y*b1.w + hr.z*b2.w + hr.w*b3.w) * hob.w + hp.w*b3.w;
            __stcs(&ob[3 * D4 + d4], o);
        }
    }
}

extern "C" void kernel_launch(void* const* d_in, const int* in_sizes, int n_in,
                              void* d_out, int out_size) {
    const float* x      = (const float*)d_in[0];  // [8,2048,4,1024]
    const float* h_res  = (const float*)d_in[1];  // [8,2048,4,4]
    const float* h_out  = (const float*)d_in[2];  // [8,2048,1024]
    const float* h_post = (const float*)d_in[3];  // [8,2048,4]
    float* out = (float*)d_out;                   // [8,2048,4,1024]

    stream_mix_kernel2<<<TOKENS / 2, 256>>>(x, h_res, h_out, h_post, out);
}